// round 8
// baseline (speedup 1.0000x reference)
#include <cuda_runtime.h>
#include <math.h>

#define N_USERS 150000
#define N_ENT   250000
#define CH      64
#define N_REL   17
#define NF      4
#define N_EDGES 1000000
#define NNZ     1000000
#define NTOT    (N_ENT + N_USERS)          // 400000 segment counters
#define NLIST   (N_EDGES + NNZ)            // 2000000 list entries
#define SCAN_B  1024
#define NB_SCAN ((NTOT + SCAN_B - 1) / SCAN_B)   // 391

// ------- static scratch: referenced ONLY from device code (never as host args)
__device__ __align__(16) float g_e1[(size_t)N_ENT   * CH];  // entity emb after hop0
__device__ __align__(16) float g_u1[(size_t)N_USERS * CH];  // user   emb after hop0
__device__ int2 g_list[NLIST];     // ent part: (tail, rel); usr part: (col, bitcast val)
__device__ int  g_cnt[NTOT];
__device__ int  g_cur[NTOT];
__device__ int  g_off[NTOT + 1];
__device__ int  g_bsum[NB_SCAN];
__device__ float g_dw[NF * CH];    // softmax(att) @ weight

// ---------------- CSR build ---------------------------------------------------
__global__ void zero_kernel() {
    int i = blockIdx.x * blockDim.x + threadIdx.x;
    if (i < NTOT) { g_cnt[i] = 0; g_cur[i] = 0; }
}

__global__ void count_kernel(const int* __restrict__ head,
                             const int* __restrict__ irow) {
    int i = blockIdx.x * blockDim.x + threadIdx.x;
    if (i >= NLIST) return;
    if (i < N_EDGES) atomicAdd(&g_cnt[head[i]], 1);
    else             atomicAdd(&g_cnt[N_ENT + irow[i - N_EDGES]], 1);
}

// block-level exclusive scan: 256 threads x 4 elems = 1024 per block
__global__ void scan1_kernel() {
    __shared__ int wsum[8];
    __shared__ int wexcl[8];
    int t = threadIdx.x, lane = t & 31, wid = t >> 5;
    int base = blockIdx.x * SCAN_B + t * 4;
    int c0 = (base + 0 < NTOT) ? g_cnt[base + 0] : 0;
    int c1 = (base + 1 < NTOT) ? g_cnt[base + 1] : 0;
    int c2 = (base + 2 < NTOT) ? g_cnt[base + 2] : 0;
    int c3 = (base + 3 < NTOT) ? g_cnt[base + 3] : 0;
    int tot = c0 + c1 + c2 + c3;
    int v = tot;
    #pragma unroll
    for (int o = 1; o < 32; o <<= 1) {
        int n = __shfl_up_sync(0xffffffffu, v, o);
        if (lane >= o) v += n;
    }
    if (lane == 31) wsum[wid] = v;
    __syncthreads();
    if (t == 0) {
        int run = 0;
        #pragma unroll
        for (int w = 0; w < 8; w++) { wexcl[w] = run; run += wsum[w]; }
    }
    __syncthreads();
    int texcl = wexcl[wid] + (v - tot);
    if (base + 0 < NTOT) g_off[base + 0] = texcl;
    if (base + 1 < NTOT) g_off[base + 1] = texcl + c0;
    if (base + 2 < NTOT) g_off[base + 2] = texcl + c0 + c1;
    if (base + 3 < NTOT) g_off[base + 3] = texcl + c0 + c1 + c2;
    if (t == 255) g_bsum[blockIdx.x] = texcl + tot;
}

__global__ void scan2_kernel() {   // single block, 512 threads
    __shared__ int sh[512];
    int t = threadIdx.x;
    int v = (t < NB_SCAN) ? g_bsum[t] : 0;
    sh[t] = v;
    __syncthreads();
    #pragma unroll
    for (int o = 1; o < 512; o <<= 1) {
        int a = (t >= o) ? sh[t - o] : 0;
        __syncthreads();
        sh[t] += a;
        __syncthreads();
    }
    if (t < NB_SCAN) g_bsum[t] = sh[t] - v;   // exclusive
}

__global__ void scan3_kernel() {
    int i = blockIdx.x * blockDim.x + threadIdx.x;
    if (i < NTOT) g_off[i] += g_bsum[i / SCAN_B];
    if (i == 0) g_off[NTOT] = NLIST;
}

__global__ void fill_kernel(const int* __restrict__ head,
                            const int* __restrict__ tail,
                            const int* __restrict__ etype,
                            const int* __restrict__ irow,
                            const int* __restrict__ icol,
                            const float* __restrict__ ival) {
    int i = blockIdx.x * blockDim.x + threadIdx.x;
    if (i >= NLIST) return;
    if (i < N_EDGES) {
        int h = head[i];
        int p = atomicAdd(&g_cur[h], 1);
        g_list[g_off[h] + p] = make_int2(tail[i], etype[i] - 1);
    } else {
        int j = i - N_EDGES;
        int r = irow[j];
        int p = atomicAdd(&g_cur[N_ENT + r], 1);
        g_list[g_off[N_ENT + r] + p] = make_int2(icol[j], __float_as_int(ival[j]));
    }
}

// ---------------- tiny: disen_weight + cor ------------------------------------
__global__ void small_kernel(const float* __restrict__ dwa,
                             const float* __restrict__ weight,
                             float* __restrict__ out_cor) {
    int t = threadIdx.x;            // 256 threads: f = t/64, c = t%64
    int f = t >> 6, c = t & 63;
    float m = -1e30f;
    #pragma unroll
    for (int j = 0; j < N_REL - 1; j++) m = fmaxf(m, dwa[f * (N_REL - 1) + j]);
    float s = 0.f;
    #pragma unroll
    for (int j = 0; j < N_REL - 1; j++) s += __expf(dwa[f * (N_REL - 1) + j] - m);
    float acc = 0.f;
    #pragma unroll
    for (int j = 0; j < N_REL - 1; j++)
        acc += (__expf(dwa[f * (N_REL - 1) + j] - m) / s) * weight[j * CH + c];
    g_dw[f * CH + c] = acc;

    if (t == 0) {
        float nrm[NF];
        for (int r = 0; r < NF; r++) {
            float ss = 0.f;
            for (int j = 0; j < N_REL - 1; j++) {
                float x = dwa[r * (N_REL - 1) + j];
                ss += x * x;
            }
            nrm[r] = sqrtf(ss);
        }
        float cor = 0.f;
        for (int a = 0; a < NF; a++)
            for (int b = a + 1; b < NF; b++) {
                float d = 0.f;
                for (int j = 0; j < N_REL - 1; j++)
                    d += dwa[a * (N_REL - 1) + j] * dwa[b * (N_REL - 1) + j];
                float g = d / (nrm[a] * nrm[b]);
                cor += g * g;
            }
        *out_cor = cor;
    }
}

// ---------------- fused gather hop over ALL nodes (entities + users) ----------
// warp per node. Half-warp per edge: sub = lane>>4 takes edges s+sub, s+sub+2,...
// lane covers 4 channels (float4). 4 edge-rows in flight per warp (2 subs x unroll2).
__global__ void __launch_bounds__(256) gather_kernel(
        const float* __restrict__ entity_emb,
        const float* __restrict__ user_emb,
        const float* __restrict__ weight,   // [N_REL-1, CH]
        const float* __restrict__ latent,   // [NF, CH]
        float* __restrict__ out_ent,
        float* __restrict__ out_usr,
        int final_hop) {
    __shared__ float shw[(N_REL - 1) * CH];    // 4KB relation weights
    __shared__ float shl[NF * CH];             // latent
    __shared__ float shd[NF * CH];             // disen_weight
    for (int i = threadIdx.x; i < (N_REL - 1) * CH; i += blockDim.x) shw[i] = weight[i];
    for (int i = threadIdx.x; i < NF * CH; i += blockDim.x) {
        shl[i] = latent[i];
        shd[i] = g_dw[i];
    }
    __syncthreads();

    int gw   = (blockIdx.x * blockDim.x + threadIdx.x) >> 5;
    int lane = threadIdx.x & 31;
    int sub  = lane >> 4;          // 0 or 1: which edge parity this half-warp takes
    int cl   = lane & 15;          // channel group: channels [4*cl, 4*cl+3]
    if (gw >= NTOT) return;
    int s = g_off[gw], e = g_off[gw + 1];

    const float4* E4 = final_hop ? reinterpret_cast<const float4*>(g_e1)
                                 : reinterpret_cast<const float4*>(entity_emb);

    if (gw < N_ENT) {
        // -------- entity: neigh = e[tail] * weight[rel], mean, l2norm ---------
        float4 a = make_float4(0.f, 0.f, 0.f, 0.f);
        int j = s + sub;
        for (; j + 2 < e; j += 4) {
            int2 p0 = g_list[j];
            int2 p1 = g_list[j + 2];
            float4 v0 = E4[(size_t)p0.x * 16 + cl];
            float4 v1 = E4[(size_t)p1.x * 16 + cl];
            float4 w0 = *reinterpret_cast<const float4*>(&shw[p0.y * CH + cl * 4]);
            float4 w1 = *reinterpret_cast<const float4*>(&shw[p1.y * CH + cl * 4]);
            a.x = fmaf(v0.x, w0.x, a.x); a.y = fmaf(v0.y, w0.y, a.y);
            a.z = fmaf(v0.z, w0.z, a.z); a.w = fmaf(v0.w, w0.w, a.w);
            a.x = fmaf(v1.x, w1.x, a.x); a.y = fmaf(v1.y, w1.y, a.y);
            a.z = fmaf(v1.z, w1.z, a.z); a.w = fmaf(v1.w, w1.w, a.w);
        }
        if (j < e) {
            int2 p0 = g_list[j];
            float4 v0 = E4[(size_t)p0.x * 16 + cl];
            float4 w0 = *reinterpret_cast<const float4*>(&shw[p0.y * CH + cl * 4]);
            a.x = fmaf(v0.x, w0.x, a.x); a.y = fmaf(v0.y, w0.y, a.y);
            a.z = fmaf(v0.z, w0.z, a.z); a.w = fmaf(v0.w, w0.w, a.w);
        }
        // combine the two half-warp partial sums (channels replicated across subs)
        a.x += __shfl_xor_sync(0xffffffffu, a.x, 16);
        a.y += __shfl_xor_sync(0xffffffffu, a.y, 16);
        a.z += __shfl_xor_sync(0xffffffffu, a.z, 16);
        a.w += __shfl_xor_sync(0xffffffffu, a.w, 16);

        float dn = 1.f / fmaxf((float)(e - s), 1.f);
        a.x *= dn; a.y *= dn; a.z *= dn; a.w *= dn;
        float ss = a.x * a.x + a.y * a.y + a.z * a.z + a.w * a.w;
        #pragma unroll
        for (int o = 8; o > 0; o >>= 1) ss += __shfl_xor_sync(0xffffffffu, ss, o);
        float inv = 1.f / fmaxf(sqrtf(ss), 1e-12f);
        a.x *= inv; a.y *= inv; a.z *= inv; a.w *= inv;

        if (final_hop) {
            float4 b  = reinterpret_cast<const float4*>(entity_emb)[(size_t)gw * 16 + cl];
            float4 e1 = reinterpret_cast<const float4*>(g_e1)[(size_t)gw * 16 + cl];
            a.x += b.x + e1.x; a.y += b.y + e1.y;
            a.z += b.z + e1.z; a.w += b.w + e1.w;
            if (sub == 0)
                reinterpret_cast<float4*>(out_ent)[(size_t)gw * 16 + cl] = a;
        } else {
            if (sub == 0)
                reinterpret_cast<float4*>(g_e1)[(size_t)gw * 16 + cl] = a;
        }
    } else {
        // -------- user: agg = sum val*e[col]; * (1 + softmax-mix); l2norm -----
        int uw = gw - N_ENT;
        const float4* U4 = final_hop ? reinterpret_cast<const float4*>(g_u1)
                                     : reinterpret_cast<const float4*>(user_emb);
        float4 uo = U4[(size_t)uw * 16 + cl];

        // score_f = u_old . latent_f  (16-lane reduce; halves compute identical)
        float p0 = uo.x * shl[0 * CH + cl * 4]     + uo.y * shl[0 * CH + cl * 4 + 1]
                 + uo.z * shl[0 * CH + cl * 4 + 2] + uo.w * shl[0 * CH + cl * 4 + 3];
        float p1 = uo.x * shl[1 * CH + cl * 4]     + uo.y * shl[1 * CH + cl * 4 + 1]
                 + uo.z * shl[1 * CH + cl * 4 + 2] + uo.w * shl[1 * CH + cl * 4 + 3];
        float p2 = uo.x * shl[2 * CH + cl * 4]     + uo.y * shl[2 * CH + cl * 4 + 1]
                 + uo.z * shl[2 * CH + cl * 4 + 2] + uo.w * shl[2 * CH + cl * 4 + 3];
        float p3 = uo.x * shl[3 * CH + cl * 4]     + uo.y * shl[3 * CH + cl * 4 + 1]
                 + uo.z * shl[3 * CH + cl * 4 + 2] + uo.w * shl[3 * CH + cl * 4 + 3];
        #pragma unroll
        for (int o = 8; o > 0; o >>= 1) {
            p0 += __shfl_xor_sync(0xffffffffu, p0, o);
            p1 += __shfl_xor_sync(0xffffffffu, p1, o);
            p2 += __shfl_xor_sync(0xffffffffu, p2, o);
            p3 += __shfl_xor_sync(0xffffffffu, p3, o);
        }
        float m = fmaxf(fmaxf(p0, p1), fmaxf(p2, p3));
        p0 = __expf(p0 - m); p1 = __expf(p1 - m);
        p2 = __expf(p2 - m); p3 = __expf(p3 - m);
        float invs = 1.f / (p0 + p1 + p2 + p3);
        p0 *= invs; p1 *= invs; p2 *= invs; p3 *= invs;

        float4 a = make_float4(0.f, 0.f, 0.f, 0.f);
        int j = s + sub;
        for (; j + 2 < e; j += 4) {
            int2 q0 = g_list[j];
            int2 q1 = g_list[j + 2];
            float4 v0 = E4[(size_t)q0.x * 16 + cl];
            float4 v1 = E4[(size_t)q1.x * 16 + cl];
            float w0 = __int_as_float(q0.y);
            float w1 = __int_as_float(q1.y);
            a.x = fmaf(v0.x, w0, a.x); a.y = fmaf(v0.y, w0, a.y);
            a.z = fmaf(v0.z, w0, a.z); a.w = fmaf(v0.w, w0, a.w);
            a.x = fmaf(v1.x, w1, a.x); a.y = fmaf(v1.y, w1, a.y);
            a.z = fmaf(v1.z, w1, a.z); a.w = fmaf(v1.w, w1, a.w);
        }
        if (j < e) {
            int2 q0 = g_list[j];
            float4 v0 = E4[(size_t)q0.x * 16 + cl];
            float w0 = __int_as_float(q0.y);
            a.x = fmaf(v0.x, w0, a.x); a.y = fmaf(v0.y, w0, a.y);
            a.z = fmaf(v0.z, w0, a.z); a.w = fmaf(v0.w, w0, a.w);
        }
        a.x += __shfl_xor_sync(0xffffffffu, a.x, 16);
        a.y += __shfl_xor_sync(0xffffffffu, a.y, 16);
        a.z += __shfl_xor_sync(0xffffffffu, a.z, 16);
        a.w += __shfl_xor_sync(0xffffffffu, a.w, 16);

        // mix = sum_f score_f * disen_weight_f ; a *= (1 + mix)
        float mx0 = p0 * shd[0 * CH + cl * 4]     + p1 * shd[1 * CH + cl * 4]
                  + p2 * shd[2 * CH + cl * 4]     + p3 * shd[3 * CH + cl * 4];
        float mx1 = p0 * shd[0 * CH + cl * 4 + 1] + p1 * shd[1 * CH + cl * 4 + 1]
                  + p2 * shd[2 * CH + cl * 4 + 1] + p3 * shd[3 * CH + cl * 4 + 1];
        float mx2 = p0 * shd[0 * CH + cl * 4 + 2] + p1 * shd[1 * CH + cl * 4 + 2]
                  + p2 * shd[2 * CH + cl * 4 + 2] + p3 * shd[3 * CH + cl * 4 + 2];
        float mx3 = p0 * shd[0 * CH + cl * 4 + 3] + p1 * shd[1 * CH + cl * 4 + 3]
                  + p2 * shd[2 * CH + cl * 4 + 3] + p3 * shd[3 * CH + cl * 4 + 3];
        a.x *= (1.f + mx0); a.y *= (1.f + mx1);
        a.z *= (1.f + mx2); a.w *= (1.f + mx3);

        float ss = a.x * a.x + a.y * a.y + a.z * a.z + a.w * a.w;
        #pragma unroll
        for (int o = 8; o > 0; o >>= 1) ss += __shfl_xor_sync(0xffffffffu, ss, o);
        float inv = 1.f / fmaxf(sqrtf(ss), 1e-12f);
        a.x *= inv; a.y *= inv; a.z *= inv; a.w *= inv;

        if (final_hop) {
            float4 b = reinterpret_cast<const float4*>(user_emb)[(size_t)uw * 16 + cl];
            a.x += b.x + uo.x; a.y += b.y + uo.y;
            a.z += b.z + uo.z; a.w += b.w + uo.w;
            if (sub == 0)
                reinterpret_cast<float4*>(out_usr)[(size_t)uw * 16 + cl] = a;
        } else {
            if (sub == 0)
                reinterpret_cast<float4*>(g_u1)[(size_t)uw * 16 + cl] = a;
        }
    }
}

// ---------------- launch ------------------------------------------------------
extern "C" void kernel_launch(void* const* d_in, const int* in_sizes, int n_in,
                              void* d_out, int out_size) {
    const float* user_emb   = (const float*)d_in[0];
    const float* entity_emb = (const float*)d_in[1];
    const float* latent     = (const float*)d_in[2];
    const float* weight     = (const float*)d_in[3];
    const float* dwa        = (const float*)d_in[4];
    const float* inter_val  = (const float*)d_in[5];
    const int*   edge_index = (const int*)d_in[6];
    const int*   edge_type  = (const int*)d_in[7];
    const int*   inter_row  = (const int*)d_in[8];
    const int*   inter_col  = (const int*)d_in[9];

    float* out     = (float*)d_out;
    float* out_ent = out;
    float* out_usr = out + (size_t)N_ENT * CH;
    float* out_cor = out + (size_t)N_ENT * CH + (size_t)N_USERS * CH;

    const int* head = edge_index;
    const int* tail = edge_index + N_EDGES;

    const int B = 256;

    // CSR build (once per launch)
    zero_kernel <<<(NTOT  + B - 1) / B, B>>>();
    count_kernel<<<(NLIST + B - 1) / B, B>>>(head, inter_row);
    scan1_kernel<<<NB_SCAN, 256>>>();
    scan2_kernel<<<1, 512>>>();
    scan3_kernel<<<(NTOT + B - 1) / B, B>>>();
    fill_kernel <<<(NLIST + B - 1) / B, B>>>(head, tail, edge_type,
                                             inter_row, inter_col, inter_val);
    small_kernel<<<1, 256>>>(dwa, weight, out_cor);

    // hop 0: raw inputs -> g_e1 / g_u1 ; hop 1: g_e1/g_u1 -> final outputs
    const int GB = (NTOT * 32 + B - 1) / B;
    gather_kernel<<<GB, B>>>(entity_emb, user_emb, weight, latent, out_ent, out_usr, 0);
    gather_kernel<<<GB, B>>>(entity_emb, user_emb, weight, latent, out_ent, out_usr, 1);
}

// round 9
// speedup vs baseline: 1.4545x; 1.4545x over previous
#include <cuda_runtime.h>
#include <math.h>

#define N_USERS 150000
#define N_ENT   250000
#define CH      64
#define N_REL   17
#define NF      4
#define N_EDGES 1000000
#define NNZ     1000000
#define NTOT    (N_ENT + N_USERS)          // 400000 segment counters
#define NLIST   (N_EDGES + NNZ)            // 2000000 list entries
#define SCAN_B  1024
#define NB_SCAN ((NTOT + SCAN_B - 1) / SCAN_B)   // 391

// ------- static scratch: referenced ONLY from device code (never as host args)
__device__ __align__(16) float g_e1[(size_t)N_ENT   * CH];  // entity emb after hop0
__device__ __align__(16) float g_u1[(size_t)N_USERS * CH];  // user   emb after hop0
__device__ int2 g_list[NLIST];     // ent part: (tail, rel); usr part: (col, bitcast val)
__device__ int  g_cnt[NTOT];
__device__ int  g_cur[NTOT];
__device__ int  g_off[NTOT + 1];
__device__ int  g_bsum[NB_SCAN];
__device__ float g_dw[NF * CH];    // softmax(att) @ weight

// ---------------- CSR build ---------------------------------------------------
__global__ void zero_kernel() {
    int i = blockIdx.x * blockDim.x + threadIdx.x;
    if (i < NTOT) { g_cnt[i] = 0; g_cur[i] = 0; }
}

__global__ void count_kernel(const int* __restrict__ head,
                             const int* __restrict__ irow) {
    int i = blockIdx.x * blockDim.x + threadIdx.x;
    if (i >= NLIST) return;
    if (i < N_EDGES) atomicAdd(&g_cnt[head[i]], 1);
    else             atomicAdd(&g_cnt[N_ENT + irow[i - N_EDGES]], 1);
}

// block-level exclusive scan: 256 threads x 4 elems = 1024 per block
__global__ void scan1_kernel() {
    __shared__ int wsum[8];
    __shared__ int wexcl[8];
    int t = threadIdx.x, lane = t & 31, wid = t >> 5;
    int base = blockIdx.x * SCAN_B + t * 4;
    int c0 = (base + 0 < NTOT) ? g_cnt[base + 0] : 0;
    int c1 = (base + 1 < NTOT) ? g_cnt[base + 1] : 0;
    int c2 = (base + 2 < NTOT) ? g_cnt[base + 2] : 0;
    int c3 = (base + 3 < NTOT) ? g_cnt[base + 3] : 0;
    int tot = c0 + c1 + c2 + c3;
    int v = tot;
    #pragma unroll
    for (int o = 1; o < 32; o <<= 1) {
        int n = __shfl_up_sync(0xffffffffu, v, o);
        if (lane >= o) v += n;
    }
    if (lane == 31) wsum[wid] = v;
    __syncthreads();
    if (t == 0) {
        int run = 0;
        #pragma unroll
        for (int w = 0; w < 8; w++) { wexcl[w] = run; run += wsum[w]; }
    }
    __syncthreads();
    int texcl = wexcl[wid] + (v - tot);
    if (base + 0 < NTOT) g_off[base + 0] = texcl;
    if (base + 1 < NTOT) g_off[base + 1] = texcl + c0;
    if (base + 2 < NTOT) g_off[base + 2] = texcl + c0 + c1;
    if (base + 3 < NTOT) g_off[base + 3] = texcl + c0 + c1 + c2;
    if (t == 255) g_bsum[blockIdx.x] = texcl + tot;
}

__global__ void scan2_kernel() {   // single block, 512 threads
    __shared__ int sh[512];
    int t = threadIdx.x;
    int v = (t < NB_SCAN) ? g_bsum[t] : 0;
    sh[t] = v;
    __syncthreads();
    #pragma unroll
    for (int o = 1; o < 512; o <<= 1) {
        int a = (t >= o) ? sh[t - o] : 0;
        __syncthreads();
        sh[t] += a;
        __syncthreads();
    }
    if (t < NB_SCAN) g_bsum[t] = sh[t] - v;   // exclusive
}

__global__ void scan3_kernel() {
    int i = blockIdx.x * blockDim.x + threadIdx.x;
    if (i < NTOT) g_off[i] += g_bsum[i / SCAN_B];
    if (i == 0) g_off[NTOT] = NLIST;
}

__global__ void fill_kernel(const int* __restrict__ head,
                            const int* __restrict__ tail,
                            const int* __restrict__ etype,
                            const int* __restrict__ irow,
                            const int* __restrict__ icol,
                            const float* __restrict__ ival) {
    int i = blockIdx.x * blockDim.x + threadIdx.x;
    if (i >= NLIST) return;
    if (i < N_EDGES) {
        int h = head[i];
        int p = atomicAdd(&g_cur[h], 1);
        g_list[g_off[h] + p] = make_int2(tail[i], etype[i] - 1);
    } else {
        int j = i - N_EDGES;
        int r = irow[j];
        int p = atomicAdd(&g_cur[N_ENT + r], 1);
        g_list[g_off[N_ENT + r] + p] = make_int2(icol[j], __float_as_int(ival[j]));
    }
}

// ---------------- tiny: disen_weight + cor ------------------------------------
__global__ void small_kernel(const float* __restrict__ dwa,
                             const float* __restrict__ weight,
                             float* __restrict__ out_cor) {
    int t = threadIdx.x;            // 256 threads: f = t/64, c = t%64
    int f = t >> 6, c = t & 63;
    float m = -1e30f;
    #pragma unroll
    for (int j = 0; j < N_REL - 1; j++) m = fmaxf(m, dwa[f * (N_REL - 1) + j]);
    float s = 0.f;
    #pragma unroll
    for (int j = 0; j < N_REL - 1; j++) s += __expf(dwa[f * (N_REL - 1) + j] - m);
    float acc = 0.f;
    #pragma unroll
    for (int j = 0; j < N_REL - 1; j++)
        acc += (__expf(dwa[f * (N_REL - 1) + j] - m) / s) * weight[j * CH + c];
    g_dw[f * CH + c] = acc;

    if (t == 0) {
        float nrm[NF];
        for (int r = 0; r < NF; r++) {
            float ss = 0.f;
            for (int j = 0; j < N_REL - 1; j++) {
                float x = dwa[r * (N_REL - 1) + j];
                ss += x * x;
            }
            nrm[r] = sqrtf(ss);
        }
        float cor = 0.f;
        for (int a = 0; a < NF; a++)
            for (int b = a + 1; b < NF; b++) {
                float d = 0.f;
                for (int j = 0; j < N_REL - 1; j++)
                    d += dwa[a * (N_REL - 1) + j] * dwa[b * (N_REL - 1) + j];
                float g = d / (nrm[a] * nrm[b]);
                cor += g * g;
            }
        *out_cor = cor;
    }
}

// ---------------- fused entity hop: gather + mean + l2norm (+final sum) -------
// warp per entity, lane owns channels [2*lane, 2*lane+1]. Unroll-4 degree loop.
__global__ void __launch_bounds__(256) ent_gather_kernel(
        const float* __restrict__ entity_emb,
        const float* __restrict__ weight,
        float* __restrict__ out_ent,
        int final_hop) {
    __shared__ float shw[(N_REL - 1) * CH];    // 4KB
    for (int i = threadIdx.x; i < (N_REL - 1) * CH; i += blockDim.x) shw[i] = weight[i];
    __syncthreads();

    int gw   = (blockIdx.x * blockDim.x + threadIdx.x) >> 5;
    int lane = threadIdx.x & 31;
    if (gw >= N_ENT) return;
    int s = g_off[gw], e = g_off[gw + 1];

    const float2* E2 = final_hop ? reinterpret_cast<const float2*>(g_e1)
                                 : reinterpret_cast<const float2*>(entity_emb);
    float ax = 0.f, ay = 0.f;
    int j = s;
    for (; j + 3 < e; j += 4) {
        int2 p0 = g_list[j];
        int2 p1 = g_list[j + 1];
        int2 p2 = g_list[j + 2];
        int2 p3 = g_list[j + 3];
        float2 v0 = E2[(size_t)p0.x * 32 + lane];
        float2 v1 = E2[(size_t)p1.x * 32 + lane];
        float2 v2 = E2[(size_t)p2.x * 32 + lane];
        float2 v3 = E2[(size_t)p3.x * 32 + lane];
        float2 w0 = *reinterpret_cast<const float2*>(&shw[p0.y * CH + lane * 2]);
        float2 w1 = *reinterpret_cast<const float2*>(&shw[p1.y * CH + lane * 2]);
        float2 w2 = *reinterpret_cast<const float2*>(&shw[p2.y * CH + lane * 2]);
        float2 w3 = *reinterpret_cast<const float2*>(&shw[p3.y * CH + lane * 2]);
        ax = fmaf(v0.x, w0.x, ax); ay = fmaf(v0.y, w0.y, ay);
        ax = fmaf(v1.x, w1.x, ax); ay = fmaf(v1.y, w1.y, ay);
        ax = fmaf(v2.x, w2.x, ax); ay = fmaf(v2.y, w2.y, ay);
        ax = fmaf(v3.x, w3.x, ax); ay = fmaf(v3.y, w3.y, ay);
    }
    for (; j < e; j++) {
        int2 p0 = g_list[j];
        float2 v0 = E2[(size_t)p0.x * 32 + lane];
        float2 w0 = *reinterpret_cast<const float2*>(&shw[p0.y * CH + lane * 2]);
        ax = fmaf(v0.x, w0.x, ax); ay = fmaf(v0.y, w0.y, ay);
    }
    float dn = 1.f / fmaxf((float)(e - s), 1.f);
    ax *= dn; ay *= dn;
    float ss = ax * ax + ay * ay;
    #pragma unroll
    for (int o = 16; o > 0; o >>= 1) ss += __shfl_xor_sync(0xffffffffu, ss, o);
    float inv = 1.f / fmaxf(sqrtf(ss), 1e-12f);
    float vx = ax * inv, vy = ay * inv;
    if (final_hop) {
        float2 b  = reinterpret_cast<const float2*>(entity_emb)[(size_t)gw * 32 + lane];
        float2 e1 = reinterpret_cast<const float2*>(g_e1)[(size_t)gw * 32 + lane];
        vx += b.x + e1.x;
        vy += b.y + e1.y;
        reinterpret_cast<float2*>(out_ent)[(size_t)gw * 32 + lane] = make_float2(vx, vy);
    } else {
        reinterpret_cast<float2*>(g_e1)[(size_t)gw * 32 + lane] = make_float2(vx, vy);
    }
}

// ---------------- fused user hop: gather + attention mix + l2norm (+final) ----
__global__ void __launch_bounds__(256) usr_gather_kernel(
        const float* __restrict__ entity_emb,
        const float* __restrict__ user_emb,
        const float* __restrict__ latent,  // [NF, CH]
        float* __restrict__ out_usr,
        int final_hop) {
    __shared__ float shl[NF * CH];   // latent, 1KB
    __shared__ float shd[NF * CH];   // disen_weight, 1KB
    for (int i = threadIdx.x; i < NF * CH; i += blockDim.x) {
        shl[i] = latent[i];
        shd[i] = g_dw[i];
    }
    __syncthreads();

    int gw   = (blockIdx.x * blockDim.x + threadIdx.x) >> 5;
    int lane = threadIdx.x & 31;
    if (gw >= N_USERS) return;
    int s = g_off[N_ENT + gw], e = g_off[N_ENT + gw + 1];

    const float2* E2 = final_hop ? reinterpret_cast<const float2*>(g_e1)
                                 : reinterpret_cast<const float2*>(entity_emb);
    const float2* U2 = final_hop ? reinterpret_cast<const float2*>(g_u1)
                                 : reinterpret_cast<const float2*>(user_emb);
    float2 uo = U2[(size_t)gw * 32 + lane];

    // score_f = u_old . latent_f (warp reduce), softmax over f
    float p0 = uo.x * shl[0 * CH + 2 * lane] + uo.y * shl[0 * CH + 2 * lane + 1];
    float p1 = uo.x * shl[1 * CH + 2 * lane] + uo.y * shl[1 * CH + 2 * lane + 1];
    float p2 = uo.x * shl[2 * CH + 2 * lane] + uo.y * shl[2 * CH + 2 * lane + 1];
    float p3 = uo.x * shl[3 * CH + 2 * lane] + uo.y * shl[3 * CH + 2 * lane + 1];
    #pragma unroll
    for (int o = 16; o > 0; o >>= 1) {
        p0 += __shfl_xor_sync(0xffffffffu, p0, o);
        p1 += __shfl_xor_sync(0xffffffffu, p1, o);
        p2 += __shfl_xor_sync(0xffffffffu, p2, o);
        p3 += __shfl_xor_sync(0xffffffffu, p3, o);
    }
    float m = fmaxf(fmaxf(p0, p1), fmaxf(p2, p3));
    p0 = __expf(p0 - m); p1 = __expf(p1 - m); p2 = __expf(p2 - m); p3 = __expf(p3 - m);
    float invs = 1.f / (p0 + p1 + p2 + p3);
    p0 *= invs; p1 *= invs; p2 *= invs; p3 *= invs;

    // gather: user_agg = sum val * e[col] ; unroll-4
    float ax = 0.f, ay = 0.f;
    int j = s;
    for (; j + 3 < e; j += 4) {
        int2 q0 = g_list[j];
        int2 q1 = g_list[j + 1];
        int2 q2 = g_list[j + 2];
        int2 q3 = g_list[j + 3];
        float2 v0 = E2[(size_t)q0.x * 32 + lane];
        float2 v1 = E2[(size_t)q1.x * 32 + lane];
        float2 v2 = E2[(size_t)q2.x * 32 + lane];
        float2 v3 = E2[(size_t)q3.x * 32 + lane];
        float w0 = __int_as_float(q0.y);
        float w1 = __int_as_float(q1.y);
        float w2 = __int_as_float(q2.y);
        float w3 = __int_as_float(q3.y);
        ax = fmaf(v0.x, w0, ax); ay = fmaf(v0.y, w0, ay);
        ax = fmaf(v1.x, w1, ax); ay = fmaf(v1.y, w1, ay);
        ax = fmaf(v2.x, w2, ax); ay = fmaf(v2.y, w2, ay);
        ax = fmaf(v3.x, w3, ax); ay = fmaf(v3.y, w3, ay);
    }
    for (; j < e; j++) {
        int2 q0 = g_list[j];
        float2 v0 = E2[(size_t)q0.x * 32 + lane];
        float w0 = __int_as_float(q0.y);
        ax = fmaf(v0.x, w0, ax); ay = fmaf(v0.y, w0, ay);
    }

    // mix and modulation: a = acc * (1 + mix)
    float mx = p0 * shd[0 * CH + 2 * lane] + p1 * shd[1 * CH + 2 * lane]
             + p2 * shd[2 * CH + 2 * lane] + p3 * shd[3 * CH + 2 * lane];
    float my = p0 * shd[0 * CH + 2 * lane + 1] + p1 * shd[1 * CH + 2 * lane + 1]
             + p2 * shd[2 * CH + 2 * lane + 1] + p3 * shd[3 * CH + 2 * lane + 1];
    float axm = ax * (1.f + mx), aym = ay * (1.f + my);
    float ss = axm * axm + aym * aym;
    #pragma unroll
    for (int o = 16; o > 0; o >>= 1) ss += __shfl_xor_sync(0xffffffffu, ss, o);
    float inv = 1.f / fmaxf(sqrtf(ss), 1e-12f);
    axm *= inv; aym *= inv;
    if (final_hop) {
        float2 b = reinterpret_cast<const float2*>(user_emb)[(size_t)gw * 32 + lane];
        axm += b.x + uo.x;   // uo IS u1 on the final hop
        aym += b.y + uo.y;
        reinterpret_cast<float2*>(out_usr)[(size_t)gw * 32 + lane] = make_float2(axm, aym);
    } else {
        reinterpret_cast<float2*>(g_u1)[(size_t)gw * 32 + lane] = make_float2(axm, aym);
    }
}

// ---------------- launch ------------------------------------------------------
extern "C" void kernel_launch(void* const* d_in, const int* in_sizes, int n_in,
                              void* d_out, int out_size) {
    const float* user_emb   = (const float*)d_in[0];
    const float* entity_emb = (const float*)d_in[1];
    const float* latent     = (const float*)d_in[2];
    const float* weight     = (const float*)d_in[3];
    const float* dwa        = (const float*)d_in[4];
    const float* inter_val  = (const float*)d_in[5];
    const int*   edge_index = (const int*)d_in[6];
    const int*   edge_type  = (const int*)d_in[7];
    const int*   inter_row  = (const int*)d_in[8];
    const int*   inter_col  = (const int*)d_in[9];

    float* out     = (float*)d_out;
    float* out_ent = out;
    float* out_usr = out + (size_t)N_ENT * CH;
    float* out_cor = out + (size_t)N_ENT * CH + (size_t)N_USERS * CH;

    const int* head = edge_index;
    const int* tail = edge_index + N_EDGES;

    const int B = 256;

    // CSR build (once per launch)
    zero_kernel <<<(NTOT  + B - 1) / B, B>>>();
    count_kernel<<<(NLIST + B - 1) / B, B>>>(head, inter_row);
    scan1_kernel<<<NB_SCAN, 256>>>();
    scan2_kernel<<<1, 512>>>();
    scan3_kernel<<<(NTOT + B - 1) / B, B>>>();
    fill_kernel <<<(NLIST + B - 1) / B, B>>>(head, tail, edge_type,
                                             inter_row, inter_col, inter_val);
    small_kernel<<<1, 256>>>(dwa, weight, out_cor);

    // hop 0: raw inputs -> g_e1 / g_u1
    ent_gather_kernel<<<(N_ENT   * 32 + B - 1) / B, B>>>(entity_emb, weight, out_ent, 0);
    usr_gather_kernel<<<(N_USERS * 32 + B - 1) / B, B>>>(entity_emb, user_emb, latent, out_usr, 0);

    // hop 1: g_e1/g_u1 -> final outputs (base + h1 + h2), written once
    ent_gather_kernel<<<(N_ENT   * 32 + B - 1) / B, B>>>(entity_emb, weight, out_ent, 1);
    usr_gather_kernel<<<(N_USERS * 32 + B - 1) / B, B>>>(entity_emb, user_emb, latent, out_usr, 1);
}